// round 5
// baseline (speedup 1.0000x reference)
#include <cuda_runtime.h>

#define B_ 2
#define NA 32768
#define NG 32
#define NC 15
#define PI_F 3.1415926f
#define TPB 128
#define NBLKX (NA / TPB)
#define TOTBLK (NBLKX * B_)

// ---------------- persistent scratch ----------------
#define F4 0xFFFFFFFFull,0xFFFFFFFFull,0xFFFFFFFFull,0xFFFFFFFFull
#define F16 F4,F4,F4,F4
__device__ unsigned long long d_gtbest[B_ * NG] = {F16, F16, F16, F16};
__device__ double d_sum_cls[B_];
__device__ double d_sum_reg[B_];
__device__ int    d_numpos[B_];
__device__ volatile int d_bar1;
__device__ int d_bar2;

// ---------------- helpers ----------------
__device__ __forceinline__ void make_quad(float cx, float cy, float w, float h,
                                          float th_deg, float* qx, float* qy,
                                          float* signed_area) {
    float ang = th_deg * (PI_F / 180.0f);
    float c = cosf(ang), s = sinf(ang);
    const float ddx[4] = {-0.5f, 0.5f, 0.5f, -0.5f};
    const float ddy[4] = {-0.5f, -0.5f, 0.5f, 0.5f};
#pragma unroll
    for (int k = 0; k < 4; k++) {
        qx[k] = cx + ddx[k] * w * c - ddy[k] * h * s;
        qy[k] = cy + ddx[k] * w * s + ddy[k] * h * c;
    }
    float sa = 0.0f;
#pragma unroll
    for (int k = 0; k < 4; k++) {
        int nk = (k + 1) & 3;
        sa += qx[k] * qy[nk] - qx[nk] * qy[k];
    }
    *signed_area = sa;
}

// ---------------- fused kernel ----------------
__global__ void __launch_bounds__(TPB) kFused(
    const float* __restrict__ cls, const float* __restrict__ reg,
    const float* __restrict__ anchors, const float* __restrict__ ann,
    float* __restrict__ out)
{
    // -------- shared --------
    __shared__ float4 g_sq[NG];
    __shared__ float4 g_aabb[NG];
    __shared__ float4 g_quad[NG][2];
    __shared__ float4 g_misc[NG];
    __shared__ unsigned long long sbest[NG];
    __shared__ unsigned long long sab[TPB];
    __shared__ unsigned short wp[TPB / 32][1024];
    __shared__ float scx[2][8][TPB];
    __shared__ float scy[2][8][TPB];
    __shared__ double swc[TPB / 32], swr[TPB / 32];
    __shared__ int    swp_[TPB / 32];
    __shared__ int    sforce[NG];

    int b = blockIdx.y;
    int t = threadIdx.x;
    int w = t >> 5, lane = t & 31;
    int i = blockIdx.x * TPB + t;

    // -------- PREFETCH loss-phase inputs (overlaps with all of phase A) --------
    float cr15[NC];
    {
        const float* cr = cls + ((size_t)b * NA + i) * NC;
#pragma unroll
        for (int c_ = 0; c_ < NC; c_++) cr15[c_] = __ldg(cr + c_);
    }
    float rr5[5];
    {
        const float* rr = reg + ((size_t)b * NA + i) * 5;
#pragma unroll
        for (int k = 0; k < 5; k++) rr5[k] = __ldg(rr + k);
    }

    // -------- GT setup --------
    if (t < NG) {
        const float* gb = ann + ((size_t)b * NG + t) * 6;
        float x0 = gb[0], y0 = gb[1], x1 = gb[2], y1 = gb[3], th = gb[4];
        float cx = (x0 + x1) * 0.5f, cy = (y0 + y1) * 0.5f;
        float gw = x1 - x0, gh = y1 - y0;
        float qx[4], qy[4], sa;
        make_quad(cx, cy, gw, gh, th, qx, qy, &sa);
        bool rev = (sa < 0.0f);
        float cqx[4], cqy[4];
#pragma unroll
        for (int k = 0; k < 4; k++) {
            int src = rev ? (3 - k) : k;
            cqx[k] = qx[src]; cqy[k] = qy[src];
        }
        g_quad[t][0] = make_float4(cqx[0], cqy[0], cqx[1], cqy[1]);
        g_quad[t][1] = make_float4(cqx[2], cqy[2], cqx[3], cqy[3]);
        float mnx = fminf(fminf(qx[0], qx[1]), fminf(qx[2], qx[3]));
        float mxx = fmaxf(fmaxf(qx[0], qx[1]), fmaxf(qx[2], qx[3]));
        float mny = fminf(fminf(qy[0], qy[1]), fminf(qy[2], qy[3]));
        float mxy = fmaxf(fmaxf(qy[0], qy[1]), fmaxf(qy[2], qy[3]));
        g_aabb[t] = make_float4(mnx - 0.01f, mny - 0.01f, mxx + 0.01f, mxy + 0.01f);
        float ss = fmaxf(gw, gh) * 0.5f;
        float s0 = cx - ss, s1 = cy - ss, s2 = cx + ss, s3 = cy + ss;
        g_sq[t] = make_float4(s0, s1, s2, s3);
        float areag_sq = (s2 - s0) * (s3 - s1);
        g_misc[t] = make_float4(0.5f * fabsf(sa), areag_sq, 0.0f, 0.0f);
        sbest[t] = 0ULL;
    }
    sab[t] = 0xFFFFFFFFull;  // iou=0, g=0
    __syncthreads();

    // -------- anchor setup --------
    const float* ab = anchors + ((size_t)b * NA + i) * 5;
    float x0 = ab[0], y0 = ab[1], x1 = ab[2], y1 = ab[3], ath = ab[4];
    float acx = (x0 + x1) * 0.5f, acy = (y0 + y1) * 0.5f;
    float aw = x1 - x0, ah = y1 - y0;

    float aqx[4], aqy[4], sa_a;
    make_quad(acx, acy, aw, ah, ath, aqx, aqy, &sa_a);
    float area_a = 0.5f * fabsf(sa_a);
    float p1x[4], p1y[4];
    {
        bool arev = (sa_a < 0.0f);
#pragma unroll
        for (int k = 0; k < 4; k++) {
            int src = arev ? (3 - k) : k;
            p1x[k] = aqx[src]; p1y[k] = aqy[src];
        }
    }
    float ssa = fmaxf(aw, ah) * 0.5f;
    float as0 = acx - ssa, as1 = acy - ssa, as2 = acx + ssa, as3 = acy + ssa;
    float area_asq = (as2 - as0) * (as3 - as1);

    // -------- prefilter: center in padded GT-quad AABB --------
    unsigned candmask = 0;
#pragma unroll 8
    for (int g = 0; g < NG; g++) {
        float4 bb = g_aabb[g];
        if (acx >= bb.x && acx <= bb.z && acy >= bb.y && acy <= bb.w)
            candmask |= (1u << g);
    }

    // -------- full gate on candidates --------
    unsigned gatemask = 0;
    {
        unsigned m = candmask;
        while (m) {
            int g = __ffs(m) - 1;
            m &= m - 1;
            float4 sq = g_sq[g];
            float lx = fmaxf(as0, sq.x), ly = fmaxf(as1, sq.y);
            float rx = fminf(as2, sq.z), ry = fminf(as3, sq.w);
            float iw = fmaxf(rx - lx, 0.0f), ih = fmaxf(ry - ly, 0.0f);
            float inter = iw * ih;
            float4 misc = g_misc[g];
            float ind = inter / (area_asq + misc.y - inter + 1e-6f);

            float4 v01 = g_quad[g][0];
            float4 v23 = g_quad[g][1];
            float qx_[4] = {v01.x, v01.z, v23.x, v23.z};
            float qy_[4] = {v01.y, v01.w, v23.y, v23.w};
            bool allp = true, alln = true;
#pragma unroll
            for (int k = 0; k < 4; k++) {
                int nk = (k + 1) & 3;
                float ex = qx_[nk] - qx_[k];
                float ey = qy_[nk] - qy_[k];
                float cr = ex * (acy - qy_[k]) - ey * (acx - qx_[k]);
                allp = allp && (cr >= 0.0f);
                alln = alln && (cr <= 0.0f);
            }
            if ((allp || alln) && (ind > 0.1f)) gatemask |= (1u << g);
        }
    }

    // -------- intra-warp compaction --------
    int cnt = __popc(gatemask);
    int acc = cnt;
#pragma unroll
    for (int off = 1; off < 32; off <<= 1) {
        int v = __shfl_up_sync(0xFFFFFFFFu, acc, off);
        if (lane >= off) acc += v;
    }
    int excl = acc - cnt;
    int T = __shfl_sync(0xFFFFFFFFu, acc, 31);
    {
        unsigned m = gatemask;
        int p = excl;
        while (m) {
            int g = __ffs(m) - 1;
            m &= m - 1;
            wp[w][p++] = (unsigned short)((lane << 5) | g);
        }
    }
    __syncwarp();

    // -------- cooperative clip (shared-memory scratch) --------
    for (int base = 0; base < T; base += 32) {
        int idx = base + lane;
        bool act = idx < T;
        unsigned e = act ? wp[w][idx] : 0u;
        int o = e >> 5;
        int g = e & 31;

        float opx[4], opy[4];
#pragma unroll
        for (int k = 0; k < 4; k++) {
            opx[k] = __shfl_sync(0xFFFFFFFFu, p1x[k], o);
            opy[k] = __shfl_sync(0xFFFFFFFFu, p1y[k], o);
        }
        float oa = __shfl_sync(0xFFFFFFFFu, area_a, o);

        if (act) {
            float4 v01 = g_quad[g][0];
            float4 v23 = g_quad[g][1];
            float q2x[4] = {v01.x, v01.z, v23.x, v23.z};
            float q2y[4] = {v01.y, v01.w, v23.y, v23.w};

            int cb = 0, n = 4;
#pragma unroll
            for (int k = 0; k < 4; k++) { scx[0][k][t] = opx[k]; scy[0][k][t] = opy[k]; }
            for (int ed = 0; ed < 4; ed++) {
                float ax = q2x[ed], ay = q2y[ed];
                float bx = q2x[(ed + 1) & 3], by = q2y[(ed + 1) & 3];
                float dx = bx - ax, dy = by - ay;
                int m2 = 0;
#pragma unroll
                for (int ii = 0; ii < 8; ii++) {
                    if (ii < n) {
                        int ni = (ii + 1 < n) ? (ii + 1) : 0;
                        float cx = scx[cb][ii][t], cy = scy[cb][ii][t];
                        float qx = scx[cb][ni][t], qy = scy[cb][ni][t];
                        float dc = dx * (cy - ay) - dy * (cx - ax);
                        float dn = dx * (qy - ay) - dy * (qx - ax);
                        bool kc = (dc >= 0.0f);
                        bool kn = (dn >= 0.0f);
                        if (kc && m2 < 8) { scx[cb ^ 1][m2][t] = cx; scy[cb ^ 1][m2][t] = cy; m2++; }
                        if ((kc != kn) && m2 < 8) {
                            float den = dc - dn;
                            if (fabsf(den) < 1e-12f) den = 1e-12f;
                            float tt = dc / den;
                            scx[cb ^ 1][m2][t] = cx + tt * (qx - cx);
                            scy[cb ^ 1][m2][t] = cy + tt * (qy - cy);
                            m2++;
                        }
                    }
                }
                cb ^= 1;
                n = m2;
                if (n == 0) break;
            }
            float ia = 0.0f;
            if (n >= 3) {
                float s = 0.0f;
#pragma unroll
                for (int ii = 0; ii < 8; ii++) {
                    if (ii < n) {
                        int ni = (ii + 1 < n) ? (ii + 1) : 0;
                        s += scx[cb][ii][t] * scy[cb][ni][t] - scx[cb][ni][t] * scy[cb][ii][t];
                    }
                }
                ia = 0.5f * fabsf(s);
            }
            float iou = ia / (oa + g_misc[g].x - ia + 1e-6f);

            unsigned bits = __float_as_uint(iou);
            unsigned long long pkv =
                ((unsigned long long)bits << 32) |
                (unsigned long long)(0xFFFFFFFFu - (unsigned)g);
            atomicMax(&sab[(w << 5) | o], pkv);
            int oi = blockIdx.x * TPB + (w << 5) + o;
            atomicMax(&sbest[g],
                      ((unsigned long long)bits << 32) |
                      (unsigned long long)(0xFFFFFFFFu - (unsigned)oi));
        }
    }

    __syncthreads();
    if (t < NG && sbest[t] != 0ULL)
        atomicMax(&d_gtbest[b * NG + t], sbest[t]);

    // -------- grid barrier (512 blocks co-resident: 128thr/63reg/~30KB -> >=4 blocks/SM) --------
    __syncthreads();
    if (t == 0) {
        __threadfence();
        atomicAdd((int*)&d_bar1, 1);
        while (d_bar1 < TOTBLK) __nanosleep(64);
        __threadfence();
    }
    __syncthreads();

    // -------- loss phase (inputs already in registers) --------
    if (t < NG) {
        unsigned long long pk = d_gtbest[b * NG + t];
        float mx = __uint_as_float((unsigned)(pk >> 32));
        int arg = (int)(0xFFFFFFFFu - (unsigned)(pk & 0xFFFFFFFFull));
        sforce[t] = (mx < 0.5f) ? arg : -1;
    }
    __syncthreads();

    unsigned long long pk = sab[t];
    float im = __uint_as_float((unsigned)(pk >> 32));
    int arg = (int)(0xFFFFFFFFu - (unsigned)(pk & 0xFFFFFFFFull));
    bool forced = false;
#pragma unroll
    for (int g = 0; g < NG; g++) forced = forced || (sforce[g] == i);
    int p = (im >= 0.5f) || forced;

    float csum = 0.0f;
    float rsum = 0.0f;

    if (p) {
        const float* gb = ann + ((size_t)b * NG + arg) * 6;
        int lab = (int)gb[5];
#pragma unroll
        for (int c_ = 0; c_ < NC; c_++) {
            float x = fminf(fmaxf(cr15[c_], 1e-4f), 0.9999f);
            if (c_ == lab) {
                float om = 1.0f - x;
                csum += 0.25f * om * om * (-__logf(x + 1e-6f));
            } else {
                csum += 0.75f * x * x * (-__logf(1.0f - x + 1e-6f));
            }
        }
        float gx0 = gb[0], gy0 = gb[1], gx1 = gb[2], gy1 = gb[3], gth = gb[4];
        float gcx = (gx0 + gx1) * 0.5f, gcy = (gy0 + gy1) * 0.5f;
        float gw = gx1 - gx0, gh = gy1 - gy0;
        float tgt5[5];
        tgt5[0] = (gcx - acx) / aw;
        tgt5[1] = (gcy - acy) / ah;
        tgt5[2] = logf(gw / aw);
        tgt5[3] = logf(gh / ah);
        tgt5[4] = (gth - ath) * (PI_F / 180.0f);
        const float beta = 1.0f / 9.0f;
#pragma unroll
        for (int k = 0; k < 5; k++) {
            float diff = fabsf(rr5[k] - tgt5[k]);
            rsum += (diff < beta) ? (0.5f * diff * diff / beta) : (diff - 0.5f * beta);
        }
    } else if (im < 0.4f) {
#pragma unroll
        for (int c_ = 0; c_ < NC; c_++) {
            float x = fminf(fmaxf(cr15[c_], 1e-4f), 0.9999f);
            csum += 0.75f * x * x * (-__logf(1.0f - x + 1e-6f));
        }
    }

    // warp reduce (double)
    double dc_ = (double)csum, dr_ = (double)rsum;
    int ip = p;
#pragma unroll
    for (int off = 16; off > 0; off >>= 1) {
        dc_ += __shfl_down_sync(0xFFFFFFFFu, dc_, off);
        dr_ += __shfl_down_sync(0xFFFFFFFFu, dr_, off);
        ip  += __shfl_down_sync(0xFFFFFFFFu, ip, off);
    }
    if (lane == 0) { swc[w] = dc_; swr[w] = dr_; swp_[w] = ip; }
    __syncthreads();
    if (t == 0) {
        double tc = 0.0, tr = 0.0;
        int tp = 0;
#pragma unroll
        for (int k = 0; k < TPB / 32; k++) { tc += swc[k]; tr += swr[k]; tp += swp_[k]; }
        atomicAdd(&d_sum_cls[b], tc);
        atomicAdd(&d_sum_reg[b], tr);
        atomicAdd(&d_numpos[b], tp);
        __threadfence();
        int old = atomicAdd(&d_bar2, 1);
        if (old == TOTBLK - 1) {
            float lc = 0.0f, lr = 0.0f;
            for (int bb = 0; bb < B_; bb++) {
                int np = d_numpos[bb];
                float npf = (float)(np > 1 ? np : 1);
                lc += (float)d_sum_cls[bb] / npf;
                lr += (np > 0) ? ((float)d_sum_reg[bb] / (npf * 5.0f)) : 0.0f;
            }
            out[0] = 5.0f * (lc / (float)B_);
            out[1] = 2.0f * (lr / (float)B_);
            for (int bb = 0; bb < B_; bb++) {
                d_sum_cls[bb] = 0.0;
                d_sum_reg[bb] = 0.0;
                d_numpos[bb] = 0;
            }
            for (int k = 0; k < B_ * NG; k++) d_gtbest[k] = 0xFFFFFFFFull;
            d_bar1 = 0;
            __threadfence();
            d_bar2 = 0;
        }
    }
}

// ---------------- launch ----------------
extern "C" void kernel_launch(void* const* d_in, const int* in_sizes, int n_in,
                              void* d_out, int out_size) {
    const float* cls     = (const float*)d_in[0];
    const float* reg     = (const float*)d_in[1];
    const float* anchors = (const float*)d_in[2];
    const float* ann     = (const float*)d_in[3];
    float* out = (float*)d_out;

    dim3 grid(NBLKX, B_);
    kFused<<<grid, TPB>>>(cls, reg, anchors, ann, out);
}

// round 6
// speedup vs baseline: 1.1289x; 1.1289x over previous
#include <cuda_runtime.h>

#define B_ 2
#define NA 32768
#define NG 32
#define NC 15
#define PI_F 3.1415926f
#define TPB 256
#define APB 128                       // anchors per block
#define NBLKX (NA / APB)
#define TOTBLK (NBLKX * B_)

// ---------------- persistent scratch ----------------
#define F4 0xFFFFFFFFull,0xFFFFFFFFull,0xFFFFFFFFull,0xFFFFFFFFull
#define F16 F4,F4,F4,F4
__device__ unsigned long long d_gtbest[B_ * NG] = {F16, F16, F16, F16};
__device__ double d_sum_cls[B_];
__device__ double d_sum_reg[B_];
__device__ int    d_numpos[B_];
__device__ volatile int d_bar1;
__device__ int d_bar2;

__device__ __forceinline__ void make_quad(float cx, float cy, float w, float h,
                                          float th_deg, float* qx, float* qy,
                                          float* signed_area) {
    float ang = th_deg * (PI_F / 180.0f);
    float c = cosf(ang), s = sinf(ang);
    const float ddx[4] = {-0.5f, 0.5f, 0.5f, -0.5f};
    const float ddy[4] = {-0.5f, -0.5f, 0.5f, 0.5f};
#pragma unroll
    for (int k = 0; k < 4; k++) {
        qx[k] = cx + ddx[k] * w * c - ddy[k] * h * s;
        qy[k] = cy + ddx[k] * w * s + ddy[k] * h * c;
    }
    float sa = 0.0f;
#pragma unroll
    for (int k = 0; k < 4; k++) {
        int nk = (k + 1) & 3;
        sa += qx[k] * qy[nk] - qx[nk] * qy[k];
    }
    *signed_area = sa;
}

// ---------------- fused kernel: 2 threads per anchor ----------------
__global__ void __launch_bounds__(TPB, 4) kFused(
    const float* __restrict__ cls, const float* __restrict__ reg,
    const float* __restrict__ anchors, const float* __restrict__ ann,
    float* __restrict__ out)
{
    // -------- shared --------
    __shared__ float4 g_sq[NG];
    __shared__ float4 g_aabb[NG];
    __shared__ float4 g_quad[NG][2];
    __shared__ float2 g_misc[NG];                   // (gt quad area, gt square area)
    __shared__ unsigned long long sbest[NG];
    __shared__ unsigned long long sab[APB];
    __shared__ unsigned short s_pairs[APB * NG];    // 8KB, true max
    __shared__ int s_np;
    __shared__ float swx[8][TPB], swy[8][TPB];      // clip write scratch (reads via regs)
    // per-anchor geometry
    __shared__ float s_aqx[4][APB], s_aqy[4][APB], s_aarea[APB];
    __shared__ float s_acx[APB], s_acy[APB], s_ssa[APB], s_asq[APB];
    __shared__ float s_aw[APB], s_ah[APB], s_ath[APB];
    __shared__ double swc[TPB / 32], swr[TPB / 32];
    __shared__ int    swp_[TPB / 32];
    __shared__ int    sforce[NG];

    int b = blockIdx.y;
    int t = threadIdx.x;
    int w = t >> 5, lane = t & 31;
    int h = t >> 7;            // half: 0 -> GTs 0..15 & classes 0..7 ; 1 -> GTs 16..31 & classes 8..14
    int ai = t & (APB - 1);    // anchor slot in block
    int i = blockIdx.x * APB + ai;

    if (t == 0) s_np = 0;

    // -------- setup: half0 = anchor geometry, half1 = GT tables + sab init --------
    if (t < APB) {
        const float* ab = anchors + ((size_t)b * NA + i) * 5;
        float x0 = ab[0], y0 = ab[1], x1 = ab[2], y1 = ab[3], ath = ab[4];
        float acx = (x0 + x1) * 0.5f, acy = (y0 + y1) * 0.5f;
        float aw = x1 - x0, ah = y1 - y0;
        float aqx[4], aqy[4], sa_a;
        make_quad(acx, acy, aw, ah, ath, aqx, aqy, &sa_a);
        bool arev = (sa_a < 0.0f);
#pragma unroll
        for (int k = 0; k < 4; k++) {
            int src = arev ? (3 - k) : k;
            s_aqx[k][ai] = aqx[src];
            s_aqy[k][ai] = aqy[src];
        }
        s_aarea[ai] = 0.5f * fabsf(sa_a);
        s_acx[ai] = acx; s_acy[ai] = acy;
        float ssa = fmaxf(aw, ah) * 0.5f;
        s_ssa[ai] = ssa;
        float as0 = acx - ssa, as1 = acy - ssa, as2 = acx + ssa, as3 = acy + ssa;
        s_asq[ai] = (as2 - as0) * (as3 - as1);
        s_aw[ai] = aw; s_ah[ai] = ah; s_ath[ai] = ath;
    } else {
        int j = t - APB;
        sab[j] = 0xFFFFFFFFull;  // iou=0, g=0
        if (j < NG) {
            const float* gb = ann + ((size_t)b * NG + j) * 6;
            float x0 = gb[0], y0 = gb[1], x1 = gb[2], y1 = gb[3], th = gb[4];
            float cx = (x0 + x1) * 0.5f, cy = (y0 + y1) * 0.5f;
            float gw = x1 - x0, gh = y1 - y0;
            float qx[4], qy[4], sa;
            make_quad(cx, cy, gw, gh, th, qx, qy, &sa);
            bool rev = (sa < 0.0f);
            float cqx[4], cqy[4];
#pragma unroll
            for (int k = 0; k < 4; k++) {
                int src = rev ? (3 - k) : k;
                cqx[k] = qx[src]; cqy[k] = qy[src];
            }
            g_quad[j][0] = make_float4(cqx[0], cqy[0], cqx[1], cqy[1]);
            g_quad[j][1] = make_float4(cqx[2], cqy[2], cqx[3], cqy[3]);
            float mnx = fminf(fminf(qx[0], qx[1]), fminf(qx[2], qx[3]));
            float mxx = fmaxf(fmaxf(qx[0], qx[1]), fmaxf(qx[2], qx[3]));
            float mny = fminf(fminf(qy[0], qy[1]), fminf(qy[2], qy[3]));
            float mxy = fmaxf(fmaxf(qy[0], qy[1]), fmaxf(qy[2], qy[3]));
            g_aabb[j] = make_float4(mnx - 0.01f, mny - 0.01f, mxx + 0.01f, mxy + 0.01f);
            float ss = fmaxf(gw, gh) * 0.5f;
            float s0 = cx - ss, s1 = cy - ss, s2 = cx + ss, s3 = cy + ss;
            g_sq[j] = make_float4(s0, s1, s2, s3);
            g_misc[j] = make_float2(0.5f * fabsf(sa), (s2 - s0) * (s3 - s1));
            sbest[j] = 0ULL;
        }
    }
    __syncthreads();

    // -------- gate: each thread covers 16 GTs of its anchor --------
    float acx = s_acx[ai], acy = s_acy[ai];
    float ssa = s_ssa[ai], area_asq = s_asq[ai];
    float as0 = acx - ssa, as1 = acy - ssa, as2 = acx + ssa, as3 = acy + ssa;

    unsigned gatemask = 0;   // bit k -> GT (h*16 + k)
    int gbase = h << 4;
#pragma unroll 4
    for (int k = 0; k < 16; k++) {
        int g = gbase + k;
        float4 bb = g_aabb[g];
        if (acx >= bb.x && acx <= bb.z && acy >= bb.y && acy <= bb.w) {
            float4 sq = g_sq[g];
            float lx = fmaxf(as0, sq.x), ly = fmaxf(as1, sq.y);
            float rx = fminf(as2, sq.z), ry = fminf(as3, sq.w);
            float iw = fmaxf(rx - lx, 0.0f), ih = fmaxf(ry - ly, 0.0f);
            float inter = iw * ih;
            float ind = inter / (area_asq + g_misc[g].y - inter + 1e-6f);

            float4 v01 = g_quad[g][0];
            float4 v23 = g_quad[g][1];
            float qx_[4] = {v01.x, v01.z, v23.x, v23.z};
            float qy_[4] = {v01.y, v01.w, v23.y, v23.w};
            bool allp = true, alln = true;
#pragma unroll
            for (int kk = 0; kk < 4; kk++) {
                int nk = (kk + 1) & 3;
                float ex = qx_[nk] - qx_[kk];
                float ey = qy_[nk] - qy_[kk];
                float cr = ex * (acy - qy_[kk]) - ey * (acx - qx_[kk]);
                allp = allp && (cr >= 0.0f);
                alln = alln && (cr <= 0.0f);
            }
            if ((allp || alln) && (ind > 0.1f)) gatemask |= (1u << k);
        }
    }

    // -------- emit pairs to block-wide list (warp-aggregated) --------
    {
        int cnt = __popc(gatemask);
        int acc = cnt;
#pragma unroll
        for (int off = 1; off < 32; off <<= 1) {
            int v = __shfl_up_sync(0xFFFFFFFFu, acc, off);
            if (lane >= off) acc += v;
        }
        int excl = acc - cnt;
        int total = __shfl_sync(0xFFFFFFFFu, acc, 31);
        int base = 0;
        if (lane == 31 && total > 0) base = atomicAdd(&s_np, total);
        base = __shfl_sync(0xFFFFFFFFu, base, 31);
        int p = base + excl;
        unsigned m = gatemask;
        while (m) {
            int k = __ffs(m) - 1;
            m &= m - 1;
            s_pairs[p++] = (unsigned short)((ai << 5) | (gbase + k));
        }
    }
    __syncthreads();

    // -------- cooperative clip: all 256 threads pull from the block list --------
    int np = s_np;
    for (int idx = t; idx < np; idx += TPB) {
        unsigned e = s_pairs[idx];
        int a = e >> 5;
        int g = e & 31;

        float curx[8], cury[8];
#pragma unroll
        for (int k = 0; k < 4; k++) { curx[k] = s_aqx[k][a]; cury[k] = s_aqy[k][a]; }
#pragma unroll
        for (int k = 4; k < 8; k++) { curx[k] = 0.0f; cury[k] = 0.0f; }
        float oa = s_aarea[a];

        float4 v01 = g_quad[g][0];
        float4 v23 = g_quad[g][1];
        float q2x[4] = {v01.x, v01.z, v23.x, v23.z};
        float q2y[4] = {v01.y, v01.w, v23.y, v23.w};

        int n = 4;
#pragma unroll
        for (int ed = 0; ed < 4; ed++) {
            float ax = q2x[ed], ay = q2y[ed];
            float bx = q2x[(ed + 1) & 3], by = q2y[(ed + 1) & 3];
            float dx = bx - ax, dy = by - ay;
            // all 8 edge distances up-front (independent FMA chains)
            float dcv[8];
#pragma unroll
            for (int ii = 0; ii < 8; ii++)
                dcv[ii] = dx * (cury[ii] - ay) - dy * (curx[ii] - ax);
            int m2 = 0;
#pragma unroll
            for (int ii = 0; ii < 8; ii++) {
                if (ii < n) {
                    float dc = dcv[ii];
                    bool nlast = (ii + 1 < n);
                    float qx = nlast ? curx[ii + 1] : curx[0];
                    float qy = nlast ? cury[ii + 1] : cury[0];
                    float dn = nlast ? dcv[ii + 1] : dcv[0];
                    bool kc = (dc >= 0.0f);
                    bool kn = (dn >= 0.0f);
                    if (kc && m2 < 8) { swx[m2][t] = curx[ii]; swy[m2][t] = cury[ii]; m2++; }
                    if ((kc != kn) && m2 < 8) {
                        float den = dc - dn;
                        if (fabsf(den) < 1e-12f) den = 1e-12f;
                        float tt = dc / den;
                        swx[m2][t] = curx[ii] + tt * (qx - curx[ii]);
                        swy[m2][t] = cury[ii] + tt * (qy - cury[ii]);
                        m2++;
                    }
                }
            }
            n = m2;
            if (n == 0) break;
#pragma unroll
            for (int ii = 0; ii < 8; ii++) { curx[ii] = swx[ii][t]; cury[ii] = swy[ii][t]; }
        }
        float ia = 0.0f;
        if (n >= 3) {
            float s = 0.0f;
#pragma unroll
            for (int ii = 0; ii < 8; ii++) {
                if (ii < n) {
                    bool nlast = (ii + 1 < n);
                    float nx = nlast ? curx[ii + 1] : curx[0];
                    float ny = nlast ? cury[ii + 1] : cury[0];
                    s += curx[ii] * ny - nx * cury[ii];
                }
            }
            ia = 0.5f * fabsf(s);
        }
        float iou = ia / (oa + g_misc[g].x - ia + 1e-6f);

        unsigned bits = __float_as_uint(iou);
        atomicMax(&sab[a],
                  ((unsigned long long)bits << 32) |
                  (unsigned long long)(0xFFFFFFFFu - (unsigned)g));
        int oi = blockIdx.x * APB + a;
        atomicMax(&sbest[g],
                  ((unsigned long long)bits << 32) |
                  (unsigned long long)(0xFFFFFFFFu - (unsigned)oi));
    }

    __syncthreads();
    if (t < NG && sbest[t] != 0ULL)
        atomicMax(&d_gtbest[b * NG + t], sbest[t]);

    // -------- grid barrier --------
    __syncthreads();
    if (t == 0) {
        __threadfence();
        atomicAdd((int*)&d_bar1, 1);
        while (d_bar1 < TOTBLK) __nanosleep(64);
        __threadfence();
    }
    __syncthreads();

    // -------- loss phase: classes split across the two halves --------
    if (t < NG) {
        unsigned long long pk = d_gtbest[b * NG + t];
        float mx = __uint_as_float((unsigned)(pk >> 32));
        int arg = (int)(0xFFFFFFFFu - (unsigned)(pk & 0xFFFFFFFFull));
        sforce[t] = (mx < 0.5f) ? arg : -1;
    }
    __syncthreads();

    unsigned long long pk = sab[ai];
    float im = __uint_as_float((unsigned)(pk >> 32));
    int arg = (int)(0xFFFFFFFFu - (unsigned)(pk & 0xFFFFFFFFull));
    bool forced = false;
#pragma unroll
    for (int g = 0; g < NG; g++) forced = forced || (sforce[g] == i);
    int p = (im >= 0.5f) || forced;

    const float* cr = cls + ((size_t)b * NA + i) * NC;
    float csum = 0.0f;
    float rsum = 0.0f;

    if (p) {
        const float* gb = ann + ((size_t)b * NG + arg) * 6;
        int lab = (int)gb[5];
        if (h == 0) {
#pragma unroll
            for (int c_ = 0; c_ < 8; c_++) {
                float x = fminf(fmaxf(cr[c_], 1e-4f), 0.9999f);
                if (c_ == lab) {
                    float om = 1.0f - x;
                    csum += 0.25f * om * om * (-__logf(x + 1e-6f));
                } else {
                    csum += 0.75f * x * x * (-__logf(1.0f - x + 1e-6f));
                }
            }
            float gx0 = gb[0], gy0 = gb[1], gx1 = gb[2], gy1 = gb[3], gth = gb[4];
            float gcx = (gx0 + gx1) * 0.5f, gcy = (gy0 + gy1) * 0.5f;
            float gw = gx1 - gx0, gh2 = gy1 - gy0;
            float aw = s_aw[ai], ah = s_ah[ai], ath = s_ath[ai];
            float tgt5[5];
            tgt5[0] = (gcx - acx) / aw;
            tgt5[1] = (gcy - acy) / ah;
            tgt5[2] = logf(gw / aw);
            tgt5[3] = logf(gh2 / ah);
            tgt5[4] = (gth - ath) * (PI_F / 180.0f);
            const float* rr = reg + ((size_t)b * NA + i) * 5;
            const float beta = 1.0f / 9.0f;
#pragma unroll
            for (int k = 0; k < 5; k++) {
                float diff = fabsf(rr[k] - tgt5[k]);
                rsum += (diff < beta) ? (0.5f * diff * diff / beta) : (diff - 0.5f * beta);
            }
        } else {
#pragma unroll
            for (int c_ = 8; c_ < NC; c_++) {
                float x = fminf(fmaxf(cr[c_], 1e-4f), 0.9999f);
                if (c_ == lab) {
                    float om = 1.0f - x;
                    csum += 0.25f * om * om * (-__logf(x + 1e-6f));
                } else {
                    csum += 0.75f * x * x * (-__logf(1.0f - x + 1e-6f));
                }
            }
        }
    } else if (im < 0.4f) {
        if (h == 0) {
#pragma unroll
            for (int c_ = 0; c_ < 8; c_++) {
                float x = fminf(fmaxf(cr[c_], 1e-4f), 0.9999f);
                csum += 0.75f * x * x * (-__logf(1.0f - x + 1e-6f));
            }
        } else {
#pragma unroll
            for (int c_ = 8; c_ < NC; c_++) {
                float x = fminf(fmaxf(cr[c_], 1e-4f), 0.9999f);
                csum += 0.75f * x * x * (-__logf(1.0f - x + 1e-6f));
            }
        }
    }

    // reduce (anchors counted once via h==0)
    double dc_ = (double)csum, dr_ = (double)rsum;
    int ip = (h == 0) ? p : 0;
#pragma unroll
    for (int off = 16; off > 0; off >>= 1) {
        dc_ += __shfl_down_sync(0xFFFFFFFFu, dc_, off);
        dr_ += __shfl_down_sync(0xFFFFFFFFu, dr_, off);
        ip  += __shfl_down_sync(0xFFFFFFFFu, ip, off);
    }
    if (lane == 0) { swc[w] = dc_; swr[w] = dr_; swp_[w] = ip; }
    __syncthreads();
    if (t == 0) {
        double tc = 0.0, tr = 0.0;
        int tp = 0;
#pragma unroll
        for (int k = 0; k < TPB / 32; k++) { tc += swc[k]; tr += swr[k]; tp += swp_[k]; }
        atomicAdd(&d_sum_cls[b], tc);
        atomicAdd(&d_sum_reg[b], tr);
        atomicAdd(&d_numpos[b], tp);
        __threadfence();
        int old = atomicAdd(&d_bar2, 1);
        if (old == TOTBLK - 1) {
            float lc = 0.0f, lr = 0.0f;
            for (int bb = 0; bb < B_; bb++) {
                int npv = d_numpos[bb];
                float npf = (float)(npv > 1 ? npv : 1);
                lc += (float)d_sum_cls[bb] / npf;
                lr += (npv > 0) ? ((float)d_sum_reg[bb] / (npf * 5.0f)) : 0.0f;
            }
            out[0] = 5.0f * (lc / (float)B_);
            out[1] = 2.0f * (lr / (float)B_);
            for (int bb = 0; bb < B_; bb++) {
                d_sum_cls[bb] = 0.0;
                d_sum_reg[bb] = 0.0;
                d_numpos[bb] = 0;
            }
            for (int k = 0; k < B_ * NG; k++) d_gtbest[k] = 0xFFFFFFFFull;
            d_bar1 = 0;
            __threadfence();
            d_bar2 = 0;
        }
    }
}

// ---------------- launch ----------------
extern "C" void kernel_launch(void* const* d_in, const int* in_sizes, int n_in,
                              void* d_out, int out_size) {
    const float* cls     = (const float*)d_in[0];
    const float* reg     = (const float*)d_in[1];
    const float* anchors = (const float*)d_in[2];
    const float* ann     = (const float*)d_in[3];
    float* out = (float*)d_out;

    dim3 grid(NBLKX, B_);
    kFused<<<grid, TPB>>>(cls, reg, anchors, ann, out);
}